// round 16
// baseline (speedup 1.0000x reference)
#include <cuda_runtime.h>
#include <cuda_bf16.h>
#include <math.h>
#include <stdint.h>

#define D       128
#define KEEP    10
#define KEEP2   12             // per-chunk list length (rescue margin)
#define NCH     9
#define POOL    (NCH * KEEP2)  // 108
#define MAXM    2048
#define MAXN    100000

// ---------------- device scratch (static globals; no allocs) ----------------
__device__ float          g_c[MAXN];                       // ||X_j||^2 - w[j]  (exact fp32)
__device__ __nv_bfloat16  g_xc[(size_t)MAXN * D];          // X hi-bf16
__device__ __nv_bfloat16  g_qc[(size_t)MAXM * D];          // Q hi-bf16
__device__ int            g_pi[MAXM * POOL];               // candidate indices

__device__ __forceinline__ float inf_f() { return __int_as_float(0x7f800000); }

// ---------------- PTX helpers ----------------
__device__ __forceinline__ uint32_t smem_u32(const void* p) {
    uint32_t a;
    asm("{ .reg .u64 t; cvta.to.shared.u64 t, %1; cvt.u32.u64 %0, t; }" : "=r"(a) : "l"(p));
    return a;
}
#define CP_COMMIT() asm volatile("cp.async.commit_group;" ::: "memory")
#define CP_WAIT0()  asm volatile("cp.async.wait_group 0;" ::: "memory")
__device__ __forceinline__ void cp16(uint32_t dst, const void* src) {
    asm volatile("cp.async.cg.shared.global [%0], [%1], 16;" :: "r"(dst), "l"(src) : "memory");
}
#define LDSM_X4(r0, r1, r2, r3, addr) \
    asm volatile("ldmatrix.sync.aligned.m8n8.x4.shared.b16 {%0,%1,%2,%3}, [%4];" \
                 : "=r"(r0), "=r"(r1), "=r"(r2), "=r"(r3) : "r"(addr))
#define MMA16816(d, a, b0, b1) \
    asm volatile("mma.sync.aligned.m16n8k16.row.col.f32.bf16.bf16.f32 " \
                 "{%0,%1,%2,%3}, {%4,%5,%6,%7}, {%8,%9}, {%0,%1,%2,%3};" \
                 : "+f"((d)[0]), "+f"((d)[1]), "+f"((d)[2]), "+f"((d)[3]) \
                 : "r"((a)[0]), "r"((a)[1]), "r"((a)[2]), "r"((a)[3]), \
                   "r"(b0), "r"(b1))

// ---------------- SMEM layout (dynamic) ----------------
// A: 2 slabs x [128 rows x 128B] SW128 = 32KB   (K=128 resident Q tile)
// B: 2 buffers x 2 slabs x 16KB = 64KB
// Sc: 128 x 132 floats = 67584B (reused for list merge at end)
#define SM_A      0
#define SM_B0     32768
#define SM_B1     65536
#define SM_SC     98304
#define SM_CS     165888       // 128 floats
#define SMEM_TOTAL 166400

// ============================================================================
// Kernel 0a: X -> bf16 hi + c[j] = ||X_j||^2 - w[j]   (warp per row)
// ============================================================================
__global__ void convert_x_prep_kernel(const float* __restrict__ X,
                                      const float* __restrict__ w, int n) {
    int row  = (blockIdx.x * blockDim.x + threadIdx.x) >> 5;
    int lane = threadIdx.x & 31;
    if (row >= n) return;
    float4 v = ((const float4*)(X + (size_t)row * D))[lane];
    __nv_bfloat162 h0 = __nv_bfloat162(__float2bfloat16(v.x), __float2bfloat16(v.y));
    __nv_bfloat162 h1 = __nv_bfloat162(__float2bfloat16(v.z), __float2bfloat16(v.w));
    size_t b = (size_t)row * D + lane * 4;
    *(__nv_bfloat162*)(g_xc + b)     = h0;
    *(__nv_bfloat162*)(g_xc + b + 2) = h1;
    float s = v.x * v.x + v.y * v.y + v.z * v.z + v.w * v.w;
    #pragma unroll
    for (int o = 16; o > 0; o >>= 1) s += __shfl_xor_sync(0xffffffffu, s, o);
    if (lane == 0) g_c[row] = s - w[row];
}

// ============================================================================
// Kernel 0b: Q -> bf16 hi   (warp per row)
// ============================================================================
__global__ void convert_q_kernel(const float* __restrict__ Q, int m) {
    int row  = (blockIdx.x * blockDim.x + threadIdx.x) >> 5;
    int lane = threadIdx.x & 31;
    if (row >= m) return;
    float4 v = ((const float4*)(Q + (size_t)row * D))[lane];
    __nv_bfloat162 h0 = __nv_bfloat162(__float2bfloat16(v.x), __float2bfloat16(v.y));
    __nv_bfloat162 h1 = __nv_bfloat162(__float2bfloat16(v.z), __float2bfloat16(v.w));
    size_t b = (size_t)row * D + lane * 4;
    *(__nv_bfloat162*)(g_qc + b)     = h0;
    *(__nv_bfloat162*)(g_qc + b + 2) = h1;
}

// ============================================================================
// Kernel 2: HMMA GEMM 128q x 128c x 128 (bf16 hi) + streaming top-12
//   grid = (NCH, m/128), block = 512 (16 warps, 4x4 grid of 32x32 warp tiles)
// ============================================================================
__device__ __forceinline__ void issue_B(uint32_t dst, int jt0, int j1, int tid) {
    // full K=128 tile: 2 slabs x (128 rows x 128B); 2048 16B segs / 512 thr
    #pragma unroll
    for (int i = 0; i < 4; i++) {
        int seg  = tid + 512 * i;
        int slab = seg >> 10;
        int r    = (seg >> 3) & 127;
        int g    = seg & 7;
        int j = min(jt0 + r, j1 - 1);
        const void* src = g_xc + (size_t)j * D + slab * 64 + g * 8;
        uint32_t off = (uint32_t)(slab * 16384)
                     + (((uint32_t)(r * 128 + g * 16)) ^ ((uint32_t)(r & 7) << 4));
        cp16(dst + off, src);
    }
    CP_COMMIT();
}

__global__ void __launch_bounds__(512, 1)
score_kernel(int m, int n)
{
    extern __shared__ char smem[];
    const uint32_t sb = smem_u32(smem);
    const int tid  = threadIdx.x;
    const int lane = tid & 31;
    const int w    = tid >> 5;          // 0..15
    const int qw   = w >> 2;            // query 32-row band
    const int cw   = w & 3;             // cand 32-col band
    const int chunk = blockIdx.x, qb = blockIdx.y * 128;

    const int per = (n + NCH - 1) / NCH;
    const int j0  = chunk * per;
    const int j1  = min(n, j0 + per);
    const int ntiles = (j1 - j0 + 127) / 128;

    float* ScF = (float*)(smem + SM_SC);
    float* cs  = (float*)(smem + SM_CS);

    // ---- resident A: 128 rows x 128 bf16, 2 SW128 slabs ----
    #pragma unroll
    for (int i = 0; i < 4; i++) {
        int seg  = tid + 512 * i;
        int slab = seg >> 10;
        int r    = (seg >> 3) & 127;
        int g    = seg & 7;
        int gq = min(qb + r, m - 1);
        const void* src = g_qc + (size_t)gq * D + slab * 64 + g * 8;
        uint32_t off = (uint32_t)(slab * 16384)
                     + (((uint32_t)(r * 128 + g * 16)) ^ ((uint32_t)(r & 7) << 4));
        cp16(sb + SM_A + off, src);
    }
    CP_COMMIT();
    issue_B(sb + SM_B0, j0, j1, tid);

    // ldmatrix base offsets (within a slab; swizzle mask depends only on row)
    uint32_t abase[2], amask[2];
    #pragma unroll
    for (int mi = 0; mi < 2; mi++) {
        uint32_t r = (uint32_t)(qw * 32 + mi * 16 + (lane & 15));
        abase[mi] = r * 128 + ((uint32_t)(lane >> 4) << 4);
        amask[mi] = (r & 7) << 4;
    }
    uint32_t bbaseL[2], bmaskL[2];
    #pragma unroll
    for (int ni = 0; ni < 2; ni++) {
        uint32_t nr = (uint32_t)(cw * 32 + ni * 16 + (lane & 7) + ((lane >> 4) << 3));
        bbaseL[ni] = nr * 128 + (((uint32_t)(lane >> 3) & 1) << 4);
        bmaskL[ni] = (nr & 7) << 4;
    }

    float tv[KEEP2]; int ti[KEEP2];
    #pragma unroll
    for (int k = 0; k < KEEP2; k++) { tv[k] = inf_f(); ti[k] = -1; }

    const uint32_t bbuf[2] = { sb + SM_B0, sb + SM_B1 };
    const int q  = tid >> 2;            // scan query (4 threads/query)
    const int hf = tid & 3;

    for (int t = 0; t < ntiles; t++) {
        int jt0 = j0 + t * 128;

        CP_WAIT0();                     // B[t] resident (and A on t==0)
        __syncthreads();                // also: prior scan done (Sc/cs reusable)
        if (tid < 128) {
            int j = jt0 + tid;
            cs[tid] = (j < j1) ? g_c[j] : inf_f();
        }
        if (t + 1 < ntiles) issue_B(bbuf[(t + 1) & 1], jt0 + 128, j1, tid);

        float acc[2][4][4];
        #pragma unroll
        for (int mi = 0; mi < 2; mi++)
            #pragma unroll
            for (int nj = 0; nj < 4; nj++)
                #pragma unroll
                for (int e = 0; e < 4; e++) acc[mi][nj][e] = 0.0f;

        const uint32_t bcur = bbuf[t & 1];
        #pragma unroll
        for (int kc = 0; kc < 2; kc++) {
            const uint32_t aslab = sb + SM_A + kc * 16384;
            const uint32_t bslab = bcur + kc * 16384;
            #pragma unroll
            for (int ks = 0; ks < 4; ks++) {
                const uint32_t kb = (uint32_t)(ks * 32);
                uint32_t a0[4], a1[4], b0[4], b1[4];
                LDSM_X4(a0[0], a0[1], a0[2], a0[3], aslab + ((abase[0] + kb) ^ amask[0]));
                LDSM_X4(a1[0], a1[1], a1[2], a1[3], aslab + ((abase[1] + kb) ^ amask[1]));
                LDSM_X4(b0[0], b0[1], b0[2], b0[3], bslab + ((bbaseL[0] + kb) ^ bmaskL[0]));
                LDSM_X4(b1[0], b1[1], b1[2], b1[3], bslab + ((bbaseL[1] + kb) ^ bmaskL[1]));
                MMA16816(acc[0][0], a0, b0[0], b0[1]);
                MMA16816(acc[0][1], a0, b0[2], b0[3]);
                MMA16816(acc[1][0], a1, b0[0], b0[1]);
                MMA16816(acc[1][1], a1, b0[2], b0[3]);
                MMA16816(acc[0][2], a0, b1[0], b1[1]);
                MMA16816(acc[0][3], a0, b1[2], b1[3]);
                MMA16816(acc[1][2], a1, b1[0], b1[1]);
                MMA16816(acc[1][3], a1, b1[2], b1[3]);
            }
        }

        // ---- epilogue: stage dots to smem (stride 132) ----
        {
            int r0 = qw * 32 + (lane >> 2);
            int c0 = cw * 32 + (lane & 3) * 2;
            #pragma unroll
            for (int mi = 0; mi < 2; mi++)
                #pragma unroll
                for (int nj = 0; nj < 4; nj++) {
                    int row = r0 + mi * 16;
                    int col = c0 + nj * 8;
                    ScF[row * 132 + col]           = acc[mi][nj][0];
                    ScF[row * 132 + col + 1]       = acc[mi][nj][1];
                    ScF[(row + 8) * 132 + col]     = acc[mi][nj][2];
                    ScF[(row + 8) * 132 + col + 1] = acc[mi][nj][3];
                }
        }
        __syncthreads();

        // ---- scan: 4 threads/query, 32 cols each, bank-skewed ----
        {
            const float* srow = ScF + q * 132;
            #pragma unroll 4
            for (int jj = 0; jj < 32; jj++) {
                int col = hf * 32 + ((jj + hf) & 31);
                float s = cs[col] - 2.0f * srow[col];
                if (s < tv[KEEP2 - 1]) {
                    tv[KEEP2 - 1] = s; ti[KEEP2 - 1] = jt0 + col;
                    #pragma unroll
                    for (int k = KEEP2 - 1; k > 0; --k) {
                        if (tv[k] < tv[k - 1]) {
                            float fv = tv[k]; tv[k] = tv[k - 1]; tv[k - 1] = fv;
                            int   iv = ti[k]; ti[k] = ti[k - 1]; ti[k - 1] = iv;
                        }
                    }
                }
            }
        }
    }

    // ---- merge the four per-query quarter-lists, write candidate indices ----
    __syncthreads();
    float* fvs = (float*)(smem + SM_SC);
    int*   ivs = (int*)(smem + SM_SC + 512 * KEEP2 * 4);
    #pragma unroll
    for (int k = 0; k < KEEP2; k++) { fvs[tid * KEEP2 + k] = tv[k]; ivs[tid * KEEP2 + k] = ti[k]; }
    __syncthreads();
    if (tid < 128 && (qb + tid) < m) {
        int p[4] = {0, 0, 0, 0};
        int base = (qb + tid) * POOL + chunk * KEEP2;
        #pragma unroll
        for (int k = 0; k < KEEP2; k++) {
            float bestv = inf_f(); int bl = 0;
            #pragma unroll
            for (int l = 0; l < 4; l++) {
                float v = (p[l] < KEEP2) ? fvs[(4 * tid + l) * KEEP2 + p[l]] : inf_f();
                if (v < bestv) { bestv = v; bl = l; }
            }
            g_pi[base + k] = ivs[(4 * tid + bl) * KEEP2 + p[bl]];
            p[bl]++;
        }
    }
}

// ============================================================================
// Kernel 3: exact fp32 rescore of 108 candidates -> exact top-10 -> max act
//   grid = m, block = 256 (8 warps: warp per candidate round)
// ============================================================================
__global__ void __launch_bounds__(256)
merge_kernel(const float* __restrict__ Q, const float* __restrict__ X,
             const float* __restrict__ w, float* __restrict__ out)
{
    __shared__ int   si[POOL];
    __shared__ float sd2[POOL];        // exact ||x-q||^2
    __shared__ float ssc[POOL];        // exact score d2 - w (augmented rank key)
    __shared__ float swv[POOL];        // w[idx]
    __shared__ float qs[D];
    __shared__ float rv[256];
    __shared__ int   ri[256];

    const int q = blockIdx.x, tid = threadIdx.x;
    const int lane = tid & 31, wp = tid >> 5;

    if (tid < POOL) si[tid] = g_pi[q * POOL + tid];
    if (tid < D)    qs[tid] = Q[(size_t)q * D + tid];
    __syncthreads();

    // exact rescore: warp per candidate
    for (int c = wp; c < POOL; c += 8) {
        int idx = si[c];
        float4 xv = __ldg(((const float4*)(X + (size_t)idx * D)) + lane);
        float4 qv = ((const float4*)qs)[lane];
        float dx = xv.x - qv.x, dy = xv.y - qv.y, dz = xv.z - qv.z, dw = xv.w - qv.w;
        float s = dx * dx + dy * dy + dz * dz + dw * dw;
        #pragma unroll
        for (int o = 16; o > 0; o >>= 1) s += __shfl_xor_sync(0xffffffffu, s, o);
        if (lane == 0) {
            float ww = __ldg(w + idx);
            sd2[c] = s; swv[c] = ww; ssc[c] = s - ww;
        }
    }
    __syncthreads();

    // exact top-10 by score, accumulate max activation
    float best = -inf_f();
    for (int r = 0; r < KEEP; r++) {
        float mv = (tid < POOL) ? ssc[tid] : inf_f();
        int   mi = (tid < POOL) ? tid : -1;
        rv[tid] = mv; ri[tid] = mi;
        __syncthreads();
        #pragma unroll
        for (int s = 128; s > 0; s >>= 1) {
            if (tid < s && rv[tid + s] < rv[tid]) { rv[tid] = rv[tid + s]; ri[tid] = ri[tid + s]; }
            __syncthreads();
        }
        if (tid == 0) {
            int sel = ri[0];
            if (sel >= 0 && rv[0] < inf_f()) {
                best = fmaxf(best, swv[sel] - sqrtf(sd2[sel]));
                ssc[sel] = inf_f();
            }
        }
        __syncthreads();
    }
    if (tid == 0) out[q] = best;
}

// ============================================================================
// launch
// ============================================================================
extern "C" void kernel_launch(void* const* d_in, const int* in_sizes, int n_in,
                              void* d_out, int out_size)
{
    const float* Xt = (const float*)d_in[0];   // (m, d) queries
    const float* X  = (const float*)d_in[1];   // (n, d) points
    const float* w  = (const float*)d_in[2];   // (n, 1)
    float* out = (float*)d_out;

    int n = in_sizes[2];
    int d = in_sizes[1] / n;
    int m = in_sizes[0] / d;
    (void)n_in; (void)out_size;

    cudaFuncSetAttribute(score_kernel, cudaFuncAttributeMaxDynamicSharedMemorySize, SMEM_TOTAL);

    // 0: convert + prep
    convert_x_prep_kernel<<<(n + 7) / 8, 256>>>(X, w, n);
    convert_q_kernel<<<(m + 7) / 8, 256>>>(Xt, m);

    // 2: HMMA GEMM + per-chunk top-12
    dim3 grid(NCH, (m + 127) / 128);
    score_kernel<<<grid, 512, SMEM_TOTAL>>>(m, n);

    // 3: exact rescore + top-10 + max act
    merge_kernel<<<m, 256>>>(Xt, X, w, out);
}